// round 6
// baseline (speedup 1.0000x reference)
#include <cuda_runtime.h>
#include <cstdint>

// Problem constants: B=2, S=2048, DM=2048, H=16, HD=128
static constexpr int B_   = 2;
static constexpr int S_   = 2048;
static constexpr int DM_  = 2048;
static constexpr int H_   = 16;
static constexpr int HD_  = 128;
static constexpr int M_   = B_ * S_;        // 4096
static constexpr int N3_  = 3 * DM_;        // 6144

// ---------------------------------------------------------------------------
// Scratch (no allocations allowed -> __device__ globals)
// ---------------------------------------------------------------------------
__device__ float g_qkv[(size_t)M_ * N3_];              // [4096, 6144] fp32
__device__ float g_q  [(size_t)B_ * H_ * S_ * HD_];    // [bh][s][d] tf32
__device__ float g_k  [(size_t)B_ * H_ * S_ * HD_];    // [bh][s][d] tf32
__device__ float g_vt [(size_t)B_ * H_ * S_ * HD_];    // [bh][d][s] tf32 (V^T)
__device__ float g_ctx[(size_t)M_ * DM_];              // [B,S,DM] tf32-rounded
__device__ float g_hsr[(size_t)M_ * DM_];              // tf32-rounded hs
__device__ float g_war[(size_t)DM_ * N3_];             // tf32-rounded w_attn
__device__ float g_wpr[(size_t)DM_ * DM_];             // tf32-rounded w_proj

// ---------------------------------------------------------------------------
// helpers
// ---------------------------------------------------------------------------
__device__ __forceinline__ uint32_t f2tf(float x) {
    uint32_t u;
    asm("cvt.rna.tf32.f32 %0, %1;" : "=r"(u) : "f"(x));
    return u;
}

__device__ __forceinline__ void mma8(float* c,
                                     uint32_t a0, uint32_t a1, uint32_t a2, uint32_t a3,
                                     uint32_t b0, uint32_t b1) {
    asm volatile(
        "mma.sync.aligned.m16n8k8.row.col.f32.tf32.tf32.f32 "
        "{%0,%1,%2,%3},{%4,%5,%6,%7},{%8,%9},{%0,%1,%2,%3};"
        : "+f"(c[0]), "+f"(c[1]), "+f"(c[2]), "+f"(c[3])
        : "r"(a0), "r"(a1), "r"(a2), "r"(a3), "r"(b0), "r"(b1));
}

__device__ __forceinline__ void ldsm4(uint32_t& r0, uint32_t& r1,
                                      uint32_t& r2, uint32_t& r3, uint32_t addr) {
    asm volatile("ldmatrix.sync.aligned.m8n8.x4.shared.b16 {%0,%1,%2,%3}, [%4];"
                 : "=r"(r0), "=r"(r1), "=r"(r2), "=r"(r3) : "r"(addr));
}

__device__ __forceinline__ void cp16(uint32_t dst_smem, const void* src) {
    asm volatile("cp.async.cg.shared.global [%0], [%1], 16;"
                 :: "r"(dst_smem), "l"(src));
}
__device__ __forceinline__ void cp_commit() {
    asm volatile("cp.async.commit_group;");
}
template <int N>
__device__ __forceinline__ void cp_wait() {
    asm volatile("cp.async.wait_group %0;" :: "n"(N));
}

// ---------------------------------------------------------------------------
// Prep: round fp32 arrays to tf32 (rna)
// ---------------------------------------------------------------------------
__global__ void round4_kernel(const float* __restrict__ in,
                              float* __restrict__ out, int n4) {
    int i = blockIdx.x * blockDim.x + threadIdx.x;
    if (i >= n4) return;
    float4 v = ((const float4*)in)[i];
    ((uint4*)out)[i] = make_uint4(f2tf(v.x), f2tf(v.y), f2tf(v.z), f2tf(v.w));
}

// ---------------------------------------------------------------------------
// tf32 GEMM, 512 threads (16 warps, 4x4), warp tile 32x32, cp.async dbuf.
// As[m=128][k=16] pitch 20, Bs[k=16][n=128] pitch 136.
// ---------------------------------------------------------------------------
static constexpr int GA_ST = 128 * 20;   // 2560 u32 per A stage
static constexpr int GB_ST = 16 * 136;   // 2176 u32 per B stage

__global__ __launch_bounds__(512, 1)
void gemm_tf32(const float* __restrict__ A, const float* __restrict__ Bm,
               const float* __restrict__ bias, float* __restrict__ C,
               int M, int N, int K) {
    __shared__ uint32_t As[2 * GA_ST];
    __shared__ uint32_t Bs[2 * GB_ST];

    const int t    = threadIdx.x;
    const int lane = t & 31;
    const int wid  = t >> 5;
    const int g    = lane >> 2;
    const int l4   = lane & 3;
    const int lrow = lane & 7;
    const int lsel = lane >> 3;
    const int wm   = (wid & 3) * 32;
    const int wn   = (wid >> 2) * 32;
    const int bm   = blockIdx.y * 128;
    const int bn   = blockIdx.x * 128;

    const uint32_t as_sm = (uint32_t)__cvta_generic_to_shared(As);
    const uint32_t bs_sm = (uint32_t)__cvta_generic_to_shared(Bs);

    // one 16B chunk each for A and B per thread per tile
    const int ar = t >> 2,  aq = (t & 3) << 2;       // A: 128 rows x 16
    const int br = t >> 5,  bq = (t & 31) << 2;      // B: 16 rows x 128

    auto issue = [&](int st, int kt) {
        const float* ap = A + (size_t)bm * K + kt * 16;
        const float* bp = Bm + (size_t)(kt * 16) * N + bn;
        cp16(as_sm + (st * GA_ST + ar * 20 + aq) * 4, ap + (size_t)ar * K + aq);
        cp16(bs_sm + (st * GB_ST + br * 136 + bq) * 4, bp + (size_t)br * N + bq);
        cp_commit();
    };

    float acc[2][4][4];
#pragma unroll
    for (int mt = 0; mt < 2; mt++)
#pragma unroll
        for (int nt = 0; nt < 4; nt++)
#pragma unroll
            for (int e = 0; e < 4; e++) acc[mt][nt][e] = 0.f;

    const int nk = K >> 4;
    issue(0, 0);

    const uint32_t a_lane = (uint32_t)((lrow + 8 * (lsel & 1)) * 20 + 4 * (lsel >> 1)) * 4;

    for (int kt = 0; kt < nk; kt++) {
        cp_wait<0>();
        __syncthreads();
        if (kt + 1 < nk) issue((kt + 1) & 1, kt + 1);

        const uint32_t a_st = as_sm + (kt & 1) * GA_ST * 4;
        const uint32_t* Bc  = Bs + (kt & 1) * GB_ST;

#pragma unroll
        for (int ks = 0; ks < 2; ks++) {
            const int k0 = ks * 8;
            uint32_t af[2][4], bf[4][2];
#pragma unroll
            for (int mt = 0; mt < 2; mt++)
                ldsm4(af[mt][0], af[mt][1], af[mt][2], af[mt][3],
                      a_st + a_lane + (uint32_t)((wm + mt * 16) * 20 + k0) * 4);
#pragma unroll
            for (int nt = 0; nt < 4; nt++) {
                const int rb = (k0 + l4) * 136 + wn + nt * 8 + g;
                bf[nt][0] = Bc[rb];
                bf[nt][1] = Bc[rb + 4 * 136];
            }
#pragma unroll
            for (int mt = 0; mt < 2; mt++)
#pragma unroll
                for (int nt = 0; nt < 4; nt++)
                    mma8(acc[mt][nt], af[mt][0], af[mt][1], af[mt][2], af[mt][3],
                         bf[nt][0], bf[nt][1]);
        }
        __syncthreads();
    }

#pragma unroll
    for (int mt = 0; mt < 2; mt++) {
#pragma unroll
        for (int nt = 0; nt < 4; nt++) {
            const int row = bm + wm + mt * 16 + g;
            const int col = bn + wn + nt * 8 + l4 * 2;
            float b0 = bias ? bias[col]     : 0.f;
            float b1 = bias ? bias[col + 1] : 0.f;
            *(float2*)(C + (size_t)row * N + col) =
                make_float2(acc[mt][nt][0] + b0, acc[mt][nt][1] + b1);
            *(float2*)(C + (size_t)(row + 8) * N + col) =
                make_float2(acc[mt][nt][2] + b0, acc[mt][nt][3] + b1);
        }
    }
}

// ---------------------------------------------------------------------------
// RoPE + scatter for Q,K only: qkv -> q,k in [bh][s][d], tf32-rounded.
// ---------------------------------------------------------------------------
__global__ void rope_kernel(const float* __restrict__ qkv,
                            const float* __restrict__ cosb,
                            const float* __restrict__ sinb,
                            float* __restrict__ q, float* __restrict__ k) {
    const int idx = blockIdx.x * blockDim.x + threadIdx.x;
    const int d = idx & 127;
    const int h = (idx >> 7) & 15;
    const int s = (idx >> 11) & 2047;
    const int b = idx >> 22;

    const float* row = qkv + (size_t)(b * S_ + s) * N3_;
    const float c  = cosb[s * HD_ + d];
    const float sn = sinb[s * HD_ + d];
    const int col   = h * HD_ + d;
    const int paird = (d < 64) ? d + 64 : d - 64;
    const float sgn = (d < 64) ? -1.f : 1.f;

    const float qv = row[col];
    const float qp = row[h * HD_ + paird];
    const float kv = row[DM_ + col];
    const float kp = row[DM_ + h * HD_ + paird];

    const size_t o = ((size_t)((b * H_ + h) * S_ + s)) * HD_ + d;
    ((uint32_t*)q)[o] = f2tf(fmaf(qv, c, sgn * qp * sn));
    ((uint32_t*)k)[o] = f2tf(fmaf(kv, c, sgn * kp * sn));
}

// ---------------------------------------------------------------------------
// V transpose: qkv v-columns -> g_vt[bh][d][s], tf32-rounded. 32x32 tiles.
// ---------------------------------------------------------------------------
__global__ void vtrans_kernel(const float* __restrict__ qkv,
                              float* __restrict__ vt) {
    __shared__ float tile[32][33];
    const int s0 = blockIdx.x * 32;
    const int d0 = blockIdx.y * 32;
    const int bh = blockIdx.z;
    const int b = bh >> 4, h = bh & 15;
    const int tx = threadIdx.x, ty = threadIdx.y;

    const float* src = qkv + (size_t)(b * S_ + s0) * N3_ + 2 * DM_ + h * HD_ + d0;
#pragma unroll
    for (int i = 0; i < 4; i++) {
        const int r = ty + i * 8;
        tile[r][tx] = src[(size_t)r * N3_ + tx];
    }
    __syncthreads();
    float* dst = vt + ((size_t)bh * HD_ + d0) * S_ + s0;
#pragma unroll
    for (int i = 0; i < 4; i++) {
        const int r = ty + i * 8;
        ((uint32_t*)dst)[(size_t)r * S_ + tx] = f2tf(tile[tx][r]);
    }
}

// ---------------------------------------------------------------------------
// Causal flash attention, 512 threads = 16 warps: 8 m-groups x 2 j-halves.
// Q-tile 128 rows; K-tile 64. Each warp: S = 16 rows x 32 cols (its j-half),
// PV partial over its j-half for all 128 d. Partial O summed in epilogue.
// Smem (u32): Qs[128][132] | K[64][132] (single, overlapped) | Vt[2][128][68]
//             | Ps[128][68] | red float4[2][8][8]
// ---------------------------------------------------------------------------
static constexpr int QS_O  = 0;                        // 16896
static constexpr int KS_O  = 16896;                    // 8448
static constexpr int VT0_O = 25344;                    // 8704
static constexpr int VT1_O = 34048;                    // 8704
static constexpr int PS_O  = 42752;                    // 8704
static constexpr int RED_O = 51456;                    // 512
static constexpr int FL_SMEM_BYTES = (RED_O + 512) * 4;   // 207872

__global__ __launch_bounds__(512, 1)
void flash_tf32(const float* __restrict__ Q, const float* __restrict__ K,
                const float* __restrict__ Vt, float* __restrict__ Ctx) {
    extern __shared__ uint32_t sm[];
    const int t    = threadIdx.x;
    const int lane = t & 31;
    const int wid  = t >> 5;
    const int g    = lane >> 2;
    const int l4   = lane & 3;
    const int lrow = lane & 7;
    const int lsel = lane >> 3;
    const int mgrp = wid & 7;
    const int jh   = wid >> 3;
    const int mrow = mgrp * 16;
    const int jbase = jh * 32;

    const int bid = blockIdx.x;
    const int qt  = ((int)gridDim.x >> 5) - 1 - (bid >> 5);  // heavy first
    const int bh  = bid & 31;
    const int q0  = qt * 128;

    const float* Qp  = Q  + (size_t)bh * S_ * HD_;
    const float* Kp  = K  + (size_t)bh * S_ * HD_;
    const float* Vtp = Vt + (size_t)bh * HD_ * S_;    // [d][s]

    const uint32_t smb = (uint32_t)__cvta_generic_to_shared(sm);
    float4* red4 = (float4*)(sm + RED_O);

    auto issueK = [&](int kt) {
        const float* kp = Kp + (size_t)(kt * 64) * HD_;
#pragma unroll
        for (int i = 0; i < 4; i++) {
            const int c = t + 512 * i;
            const int kj = c >> 5, kq = (c & 31) << 2;
            cp16(smb + (KS_O + kj * 132 + kq) * 4, kp + (size_t)kj * HD_ + kq);
        }
        cp_commit();
    };
    auto issueV = [&](int st, int kt) {
        const uint32_t vb = smb + (st ? VT1_O : VT0_O) * 4;
        const int vcol = kt * 64;
#pragma unroll
        for (int i = 0; i < 4; i++) {
            const int c = t + 512 * i;
            const int vd = c >> 4, vq = (c & 15) << 2;
            cp16(vb + (vd * 68 + vq) * 4, Vtp + (size_t)vd * S_ + vcol + vq);
        }
        cp_commit();
    };

    // prologue: load Q tile (rows q0..q0+127) + K(0) + Vt(0)
    {
#pragma unroll
        for (int i = 0; i < 8; i++) {
            const int c = t + 512 * i;
            const int r = c >> 5, cq = (c & 31) << 2;
            cp16(smb + (QS_O + r * 132 + cq) * 4, Qp + (size_t)(q0 + r) * HD_ + cq);
        }
        cp_commit();
    }
    issueK(0);
    issueV(0, 0);

    float o[16][4];
#pragma unroll
    for (int nt = 0; nt < 16; nt++)
#pragma unroll
        for (int e = 0; e < 4; e++) o[nt][e] = 0.f;
    float m0 = -1e30f, m1 = -1e30f, li0 = 0.f, li1 = 0.f;
    const float scale = 0.08838834764831845f;

    // lane-invariant ldsm address parts (bytes)
    const uint32_t qa_lane = (uint32_t)((mrow + lrow + 8 * (lsel & 1)) * 132 +
                                        4 * (lsel >> 1)) * 4;
    const uint32_t kb_lane = (uint32_t)(lrow * 132 + 4 * lsel) * 4;
    const uint32_t vb_lane = (uint32_t)(lrow * 68 + 4 * lsel) * 4;
    const uint32_t pa_lane = (uint32_t)((mrow + lrow + 8 * (lsel & 1)) * 68 +
                                        4 * (lsel >> 1)) * 4;
    const uint32_t qs_byte = smb + QS_O * 4;
    const uint32_t ks_byte = smb + KS_O * 4;
    const uint32_t ps_byte = smb + PS_O * 4;

    const int nkt = 2 * qt + 2;
    for (int kt = 0; kt < nkt; kt++) {
        __syncthreads();                       // prior PV done with Vt buf / Ps / red
        if (kt + 1 < nkt) { issueV((kt + 1) & 1, kt + 1); cp_wait<1>(); }
        else              { cp_wait<0>(); }
        __syncthreads();                       // K(kt), Vt(kt) (and Q on kt=0) visible

        const uint32_t vt_byte = smb + ((kt & 1) ? VT1_O : VT0_O) * 4;
        const int k0g = kt * 64;

        // ---- S = Q K^T : 16 rows x 32 cols (this warp's j-half) ----
        float sc[4][4];
#pragma unroll
        for (int nt = 0; nt < 4; nt++)
#pragma unroll
            for (int e = 0; e < 4; e++) sc[nt][e] = 0.f;

#pragma unroll
        for (int p = 0; p < 8; p++) {          // ks pair 2p, 2p+1
            uint32_t qa[4], qb[4];
            ldsm4(qa[0], qa[1], qa[2], qa[3], qs_byte + qa_lane + (uint32_t)(16 * p) * 4);
            ldsm4(qb[0], qb[1], qb[2], qb[3], qs_byte + qa_lane + (uint32_t)(16 * p + 8) * 4);
#pragma unroll
            for (int nt = 0; nt < 4; nt++) {
                uint32_t b0, b1, b2, b3;
                ldsm4(b0, b1, b2, b3,
                      ks_byte + kb_lane + (uint32_t)((jbase + nt * 8) * 132 + 16 * p) * 4);
                mma8(sc[nt], qa[0], qa[1], qa[2], qa[3], b0, b1);
                mma8(sc[nt], qb[0], qb[1], qb[2], qb[3], b2, b3);
            }
        }

        // ---- scale + causal mask ----
        const bool need_mask = (kt >= 2 * qt);
        const int row0 = q0 + mrow + g;
        const int row1 = row0 + 8;
#pragma unroll
        for (int nt = 0; nt < 4; nt++) {
            const int col = k0g + jbase + nt * 8 + l4 * 2;
#pragma unroll
            for (int e = 0; e < 4; e++) sc[nt][e] *= scale;
            if (need_mask) {
                if (col     > row0) sc[nt][0] = -1e30f;
                if (col + 1 > row0) sc[nt][1] = -1e30f;
                if (col     > row1) sc[nt][2] = -1e30f;
                if (col + 1 > row1) sc[nt][3] = -1e30f;
            }
        }

        // ---- softmax: local max/sum, one cross-warp exchange ----
        float L0 = -1e30f, L1 = -1e30f;
#pragma unroll
        for (int nt = 0; nt < 4; nt++) {
            L0 = fmaxf(L0, fmaxf(sc[nt][0], sc[nt][1]));
            L1 = fmaxf(L1, fmaxf(sc[nt][2], sc[nt][3]));
        }
        L0 = fmaxf(L0, __shfl_xor_sync(0xffffffffu, L0, 1));
        L0 = fmaxf(L0, __shfl_xor_sync(0xffffffffu, L0, 2));
        L1 = fmaxf(L1, __shfl_xor_sync(0xffffffffu, L1, 1));
        L1 = fmaxf(L1, __shfl_xor_sync(0xffffffffu, L1, 2));

        float s0 = 0.f, s1 = 0.f;
#pragma unroll
        for (int nt = 0; nt < 4; nt++) {
            sc[nt][0] = __expf(sc[nt][0] - L0);
            sc[nt][1] = __expf(sc[nt][1] - L0);
            sc[nt][2] = __expf(sc[nt][2] - L1);
            sc[nt][3] = __expf(sc[nt][3] - L1);
            s0 += sc[nt][0] + sc[nt][1];
            s1 += sc[nt][2] + sc[nt][3];
        }
        s0 += __shfl_xor_sync(0xffffffffu, s0, 1);
        s0 += __shfl_xor_sync(0xffffffffu, s0, 2);
        s1 += __shfl_xor_sync(0xffffffffu, s1, 1);
        s1 += __shfl_xor_sync(0xffffffffu, s1, 2);

        if (l4 == 0) red4[jh * 64 + mgrp * 8 + g] = make_float4(L0, s0, L1, s1);
        __syncthreads();                       // exchange visible
        const float4 ra = red4[mgrp * 8 + g];
        const float4 rb = red4[64 + mgrp * 8 + g];

        const float mn0 = fmaxf(m0, fmaxf(ra.x, rb.x));
        const float mn1 = fmaxf(m1, fmaxf(ra.z, rb.z));
        const float corr0 = __expf(m0 - mn0), corr1 = __expf(m1 - mn1);
        const float sum0 = ra.y * __expf(ra.x - mn0) + rb.y * __expf(rb.x - mn0);
        const float sum1 = ra.w * __expf(ra.z - mn1) + rb.w * __expf(rb.z - mn1);
        li0 = li0 * corr0 + sum0; m0 = mn0;
        li1 = li1 * corr1 + sum1; m1 = mn1;
        const float f0 = __expf(L0 - mn0), f1 = __expf(L1 - mn1);
#pragma unroll
        for (int nt = 0; nt < 4; nt++) {
            sc[nt][0] *= f0; sc[nt][1] *= f0;
            sc[nt][2] *= f1; sc[nt][3] *= f1;
        }
#pragma unroll
        for (int nt = 0; nt < 16; nt++) {
            o[nt][0] *= corr0; o[nt][1] *= corr0;
            o[nt][2] *= corr1; o[nt][3] *= corr1;
        }

        // ---- write P (this warp's 32 cols) ----
        {
            uint32_t* Ps = sm + PS_O;
#pragma unroll
            for (int nt = 0; nt < 4; nt++) {
                const int cb = jbase + nt * 8 + l4 * 2;
                *(uint2*)(&Ps[(mrow + g) * 68 + cb]) =
                    make_uint2(f2tf(sc[nt][0]), f2tf(sc[nt][1]));
                *(uint2*)(&Ps[(mrow + g + 8) * 68 + cb]) =
                    make_uint2(f2tf(sc[nt][2]), f2tf(sc[nt][3]));
            }
        }
        __syncthreads();                       // P complete; S done reading K
        if (kt + 1 < nkt) issueK(kt + 1);      // overlap K load with PV

        // ---- O_partial += P[:, jhalf] V[jhalf, :] ----
#pragma unroll
        for (int p = 0; p < 2; p++) {          // 16-j chunks within the half
            const int jc = jbase + 16 * p;
            uint32_t pa0[4], pa1[4];
            ldsm4(pa0[0], pa0[1], pa0[2], pa0[3], ps_byte + pa_lane + (uint32_t)jc * 4);
            ldsm4(pa1[0], pa1[1], pa1[2], pa1[3], ps_byte + pa_lane + (uint32_t)(jc + 8) * 4);
#pragma unroll
            for (int nt = 0; nt < 16; nt++) {
                uint32_t b0, b1, b2, b3;
                ldsm4(b0, b1, b2, b3,
                      vt_byte + vb_lane + (uint32_t)(nt * 8 * 68 + jc) * 4);
                mma8(o[nt], pa0[0], pa0[1], pa0[2], pa0[3], b0, b1);
                mma8(o[nt], pa1[0], pa1[1], pa1[2], pa1[3], b2, b3);
            }
        }
    }

    // ---- epilogue: merge j-half partials (reuse Qs region), normalize ----
    float* Ob = (float*)(sm + QS_O);           // [128][132]
    __syncthreads();                           // everyone past final S (Qs free)
    if (jh == 1) {
#pragma unroll
        for (int nt = 0; nt < 16; nt++) {
            const int cb = nt * 8 + l4 * 2;
            *(float2*)(&Ob[(mrow + g) * 132 + cb])     = make_float2(o[nt][0], o[nt][1]);
            *(float2*)(&Ob[(mrow + g + 8) * 132 + cb]) = make_float2(o[nt][2], o[nt][3]);
        }
    }
    __syncthreads();
    if (jh == 0) {
        const int b = bh >> 4;
        const int h = bh & 15;
        const float inv0 = 1.f / li0, inv1 = 1.f / li1;
        const int r0 = q0 + mrow + g;
#pragma unroll
        for (int nt = 0; nt < 16; nt++) {
            const int cb = nt * 8 + l4 * 2;
            const float2 p0 = *(const float2*)(&Ob[(mrow + g) * 132 + cb]);
            const float2 p1 = *(const float2*)(&Ob[(mrow + g + 8) * 132 + cb]);
            const int col = h * HD_ + cb;
            uint32_t* c0 = (uint32_t*)(Ctx + (size_t)(b * S_ + r0) * DM_ + col);
            uint32_t* c1 = (uint32_t*)(Ctx + (size_t)(b * S_ + r0 + 8) * DM_ + col);
            *(uint2*)c0 = make_uint2(f2tf((o[nt][0] + p0.x) * inv0),
                                     f2tf((o[nt][1] + p0.y) * inv0));
            *(uint2*)c1 = make_uint2(f2tf((o[nt][2] + p1.x) * inv1),
                                     f2tf((o[nt][3] + p1.y) * inv1));
        }
    }
}

// ---------------------------------------------------------------------------
// Launch orchestration
// ---------------------------------------------------------------------------
extern "C" void kernel_launch(void* const* d_in, const int* in_sizes, int n_in,
                              void* d_out, int out_size) {
    const float* hs     = (const float*)d_in[0];
    const float* cosb   = (const float*)d_in[1];
    const float* sinb   = (const float*)d_in[2];
    const float* w_attn = (const float*)d_in[3];
    const float* b_attn = (const float*)d_in[4];
    const float* w_proj = (const float*)d_in[5];
    float* out = (float*)d_out;

    float *qkv, *q, *k, *vt, *ctx, *hsr, *war, *wpr;
    cudaGetSymbolAddress((void**)&qkv, g_qkv);
    cudaGetSymbolAddress((void**)&q,   g_q);
    cudaGetSymbolAddress((void**)&k,   g_k);
    cudaGetSymbolAddress((void**)&vt,  g_vt);
    cudaGetSymbolAddress((void**)&ctx, g_ctx);
    cudaGetSymbolAddress((void**)&hsr, g_hsr);
    cudaGetSymbolAddress((void**)&war, g_war);
    cudaGetSymbolAddress((void**)&wpr, g_wpr);

    // 0) pre-round operands to tf32
    {
        int n4;
        n4 = (M_ * DM_) / 4;
        round4_kernel<<<(n4 + 255) / 256, 256>>>(hs, hsr, n4);
        n4 = (DM_ * N3_) / 4;
        round4_kernel<<<(n4 + 255) / 256, 256>>>(w_attn, war, n4);
        n4 = (DM_ * DM_) / 4;
        round4_kernel<<<(n4 + 255) / 256, 256>>>(w_proj, wpr, n4);
    }
    // 1) QKV GEMM + bias
    {
        dim3 grid(N3_ / 128, M_ / 128);
        gemm_tf32<<<grid, 512>>>(hsr, war, b_attn, qkv, M_, N3_, DM_);
    }
    // 2a) RoPE for Q,K
    {
        const int total = B_ * S_ * H_ * HD_;
        rope_kernel<<<total / 256, 256>>>(qkv, cosb, sinb, q, k);
    }
    // 2b) V transpose to [bh][d][s]
    {
        dim3 grid(S_ / 32, HD_ / 32, B_ * H_);
        vtrans_kernel<<<grid, dim3(32, 8)>>>(qkv, vt);
    }
    // 3) Causal flash attention
    {
        cudaFuncSetAttribute(flash_tf32,
                             cudaFuncAttributeMaxDynamicSharedMemorySize,
                             FL_SMEM_BYTES);
        flash_tf32<<<(S_ / 128) * B_ * H_, 512, FL_SMEM_BYTES>>>(q, k, vt, ctx);
    }
    // 4) Projection GEMM
    {
        dim3 grid(DM_ / 128, M_ / 128);
        gemm_tf32<<<grid, 512>>>(ctx, wpr, nullptr, out, M_, DM_, DM_);
    }
}